// round 7
// baseline (speedup 1.0000x reference)
#include <cuda_runtime.h>

#define IMD 224
#define HWPX (IMD * IMD)
#define HALO 40          // 32 + 2*4 halo
#define HR   4           // halo radius

// Output tile: 32 x-values (slow dim of p) x 32 y-values (fast dim).
// Gathers served from a channel-interleaved 40x40 float4 smem tile
// (one LDS.128 = all 3 channels of a tap). Out-of-halo taps (|c|>4,
// prob ~6e-5) fall back to global loads with the reference's flat clip.
// im1 and im2 are processed sequentially reusing one tile buffer.

__global__ __launch_bounds__(256, 4) void vm_kernel(
    const float* __restrict__ im1, const float* __restrict__ im2,
    const float* __restrict__ C,   const float* __restrict__ M1,
    const float* __restrict__ M2,  float* __restrict__ out)
{
    __shared__ float sA[32][33];        // C0  -> out c0
    __shared__ float sB[32][33];        // C1  -> out c1
    __shared__ float sD[32][33];        // M1  -> out c2
    __shared__ float sE[32][33];        // M2
    __shared__ float4 stile[HALO][HALO];  // 25.6 KB image tile (c0,c1,c2,pad)

    const int tid = threadIdx.x;
    const int n  = blockIdx.z;
    const int x0 = blockIdx.y * 32;
    const int y0 = blockIdx.x * 32;
    const int xh0 = x0 - HR;            // halo origin in nx (fast image dim)
    const int yh0 = y0 - HR;            // halo origin in ny (slow image dim)

    const float* __restrict__ Cb0 = C  + (size_t)n * 2 * HWPX;
    const float* __restrict__ Cb1 = Cb0 + HWPX;
    const float* __restrict__ M1b = M1 + (size_t)n * HWPX;
    const float* __restrict__ M2b = M2 + (size_t)n * HWPX;
    const float* __restrict__ I1b = im1 + (size_t)n * 3 * HWPX;
    const float* __restrict__ I2b = im2 + (size_t)n * 3 * HWPX;

    // ---- Phase 1a: vectorized coalesced C/M tile load ----
    {
        const int pdx = tid >> 3;          // 0..31
        const int pdy = (tid & 7) * 4;     // 0,4,...,28
        const int g   = (x0 + pdx) * IMD + (y0 + pdy);   // 16B aligned
        float4 a = *(const float4*)(Cb0 + g);
        float4 b = *(const float4*)(Cb1 + g);
        float4 d = *(const float4*)(M1b + g);
        float4 e = *(const float4*)(M2b + g);
        sA[pdx][pdy] = a.x; sA[pdx][pdy+1] = a.y; sA[pdx][pdy+2] = a.z; sA[pdx][pdy+3] = a.w;
        sB[pdx][pdy] = b.x; sB[pdx][pdy+1] = b.y; sB[pdx][pdy+2] = b.z; sB[pdx][pdy+3] = b.w;
        sD[pdx][pdy] = d.x; sD[pdx][pdy+1] = d.y; sD[pdx][pdy+2] = d.z; sD[pdx][pdy+3] = d.w;
        sE[pdx][pdy] = e.x; sE[pdx][pdy+1] = e.y; sE[pdx][pdy+2] = e.z; sE[pdx][pdy+3] = e.w;
    }

    // ---- Phase 1b: im1 halo tile (coalesced in nx; same flat clip as ref) ----
#pragma unroll
    for (int i = tid; i < HALO * HALO; i += 256) {
        int tiy = i / HALO, tix = i - tiy * HALO;
        int ind = (xh0 + tix) + IMD * (yh0 + tiy);
        ind = min(max(ind, 0), HWPX - 1);
        stile[tiy][tix] = make_float4(__ldg(I1b + ind),
                                      __ldg(I1b + HWPX + ind),
                                      __ldg(I1b + 2 * HWPX + ind), 0.0f);
    }
    __syncthreads();

    const int dx = tid & 31;        // lane -> x (taps roughly lane-consecutive)
    const int wp = tid >> 5;        // warp 0..7

    float c0r[4], c1r[4], a0[4], a1[4], a2[4];

    // ---- Phase 2a: sample im1 at (x + c0, y + c1), scale by M1 ----
#pragma unroll
    for (int k = 0; k < 4; k++) {
        const int dy = wp + k * 8;
        const float c0 = sA[dx][dy];
        const float c1 = sB[dx][dy];
        const float m1 = sD[dx][dy];
        c0r[k] = c0; c1r[k] = c1;
        const float px = (float)(x0 + dx) + c0;
        const float py = (float)(y0 + dy) + c1;

        float fx = floorf(px), cx = ceilf(px);
        float fy = floorf(py), cy = ceilf(py);
        float wfx = 1.0f - (px - fx), wcx = 1.0f - (cx - px);
        float wfy = 1.0f - (py - fy), wcy = 1.0f - (cy - py);
        int ifx = (int)fx, icx = (int)cx, ify = (int)fy, icy = (int)cy;

        float o0 = 0.f, o1 = 0.f, o2 = 0.f;
        auto tap = [&](int nx, int ny, float w) {
            int tx = nx - xh0, ty = ny - yh0;
            float v0, v1, v2;
            if ((unsigned)tx < (unsigned)HALO && (unsigned)ty < (unsigned)HALO) {
                float4 t = stile[ty][tx];
                v0 = t.x; v1 = t.y; v2 = t.z;
            } else {
                int ind = min(max(nx + IMD * ny, 0), HWPX - 1);
                v0 = __ldg(I1b + ind);
                v1 = __ldg(I1b + HWPX + ind);
                v2 = __ldg(I1b + 2 * HWPX + ind);
            }
            o0 += w * v0; o1 += w * v1; o2 += w * v2;
        };
        tap(ifx, ify, wfx * wfy);
        tap(icx, ify, wcx * wfy);
        tap(ifx, icy, wfx * wcy);
        tap(icx, icy, wcx * wcy);

        a0[k] = o0 * m1; a1[k] = o1 * m1; a2[k] = o2 * m1;
    }
    __syncthreads();   // all im1 tile reads done

    // ---- Phase 1c: im2 halo tile into the same buffer ----
#pragma unroll
    for (int i = tid; i < HALO * HALO; i += 256) {
        int tiy = i / HALO, tix = i - tiy * HALO;
        int ind = (xh0 + tix) + IMD * (yh0 + tiy);
        ind = min(max(ind, 0), HWPX - 1);
        stile[tiy][tix] = make_float4(__ldg(I2b + ind),
                                      __ldg(I2b + HWPX + ind),
                                      __ldg(I2b + 2 * HWPX + ind), 0.0f);
    }
    __syncthreads();

    // ---- Phase 2b: sample im2 at (x - c0, y - c1), scale by M2, combine ----
#pragma unroll
    for (int k = 0; k < 4; k++) {
        const int dy = wp + k * 8;
        const float m2 = sE[dx][dy];
        const float px = (float)(x0 + dx) - c0r[k];
        const float py = (float)(y0 + dy) - c1r[k];

        float fx = floorf(px), cx = ceilf(px);
        float fy = floorf(py), cy = ceilf(py);
        float wfx = 1.0f - (px - fx), wcx = 1.0f - (cx - px);
        float wfy = 1.0f - (py - fy), wcy = 1.0f - (cy - py);
        int ifx = (int)fx, icx = (int)cx, ify = (int)fy, icy = (int)cy;

        float o0 = 0.f, o1 = 0.f, o2 = 0.f;
        auto tap = [&](int nx, int ny, float w) {
            int tx = nx - xh0, ty = ny - yh0;
            float v0, v1, v2;
            if ((unsigned)tx < (unsigned)HALO && (unsigned)ty < (unsigned)HALO) {
                float4 t = stile[ty][tx];
                v0 = t.x; v1 = t.y; v2 = t.z;
            } else {
                int ind = min(max(nx + IMD * ny, 0), HWPX - 1);
                v0 = __ldg(I2b + ind);
                v1 = __ldg(I2b + HWPX + ind);
                v2 = __ldg(I2b + 2 * HWPX + ind);
            }
            o0 += w * v0; o1 += w * v1; o2 += w * v2;
        };
        tap(ifx, ify, wfx * wfy);
        tap(icx, ify, wcx * wfy);
        tap(ifx, icy, wfx * wcy);
        tap(icx, icy, wcx * wcy);

        // Owner-private cells: safe to overwrite without a barrier.
        sA[dx][dy] = a0[k] + o0 * m2;
        sB[dx][dy] = a1[k] + o1 * m2;
        sD[dx][dy] = a2[k] + o2 * m2;
    }
    __syncthreads();

    // ---- Phase 3: vectorized coalesced store ----
    {
        float* __restrict__ ob = out + (size_t)n * 3 * HWPX;
        const int pdx = tid >> 3;
        const int pdy = (tid & 7) * 4;
        const int g   = (x0 + pdx) * IMD + (y0 + pdy);   // 16B aligned
        float4 v;
        v.x = sA[pdx][pdy]; v.y = sA[pdx][pdy+1]; v.z = sA[pdx][pdy+2]; v.w = sA[pdx][pdy+3];
        *(float4*)(ob + g) = v;
        v.x = sB[pdx][pdy]; v.y = sB[pdx][pdy+1]; v.z = sB[pdx][pdy+2]; v.w = sB[pdx][pdy+3];
        *(float4*)(ob + HWPX + g) = v;
        v.x = sD[pdx][pdy]; v.y = sD[pdx][pdy+1]; v.z = sD[pdx][pdy+2]; v.w = sD[pdx][pdy+3];
        *(float4*)(ob + 2 * HWPX + g) = v;
    }
}

extern "C" void kernel_launch(void* const* d_in, const int* in_sizes, int n_in,
                              void* d_out, int out_size)
{
    const float* im1 = (const float*)d_in[0];
    const float* im2 = (const float*)d_in[1];
    const float* C   = (const float*)d_in[2];
    const float* M1  = (const float*)d_in[3];
    const float* M2  = (const float*)d_in[4];
    float* out = (float*)d_out;

    dim3 grid(IMD / 32, IMD / 32, 64);  // (7, 7, 64)
    vm_kernel<<<grid, 256>>>(im1, im2, C, M1, M2, out);
}

// round 8
// speedup vs baseline: 1.2392x; 1.2392x over previous
#include <cuda_runtime.h>

#define IMD 224
#define HWPX (IMD * IMD)

// Tile: 32 x-values (slow dim of p) x 32 y-values (fast dim).
// Phase 1: float4-vectorized coalesced loads of C0,C1,M1,M2 into padded smem.
// Phase 2: threads remapped x-fast so gather index ind = nx + 224*ny is
//          coalesced across the warp; results written straight back to the
//          owner-private smem cells per k-slice.
// Phase 3: float4-vectorized coalesced stores.
__global__ __launch_bounds__(256, 6) void vm_kernel(
    const float* __restrict__ im1, const float* __restrict__ im2,
    const float* __restrict__ C,   const float* __restrict__ M1,
    const float* __restrict__ M2,  float* __restrict__ out)
{
    __shared__ float sA[32][33];  // C0  -> out c0
    __shared__ float sB[32][33];  // C1  -> out c1
    __shared__ float sD[32][33];  // M1  -> out c2
    __shared__ float sE[32][33];  // M2

    const int tid = threadIdx.x;
    const int n  = blockIdx.z;
    const int x0 = blockIdx.y * 32;
    const int y0 = blockIdx.x * 32;

    const float* __restrict__ Cb0 = C  + (size_t)n * 2 * HWPX;
    const float* __restrict__ Cb1 = Cb0 + HWPX;
    const float* __restrict__ M1b = M1 + (size_t)n * HWPX;
    const float* __restrict__ M2b = M2 + (size_t)n * HWPX;
    const float* __restrict__ I1b = im1 + (size_t)n * 3 * HWPX;
    const float* __restrict__ I2b = im2 + (size_t)n * 3 * HWPX;

    // ---- Phase 1: vectorized coalesced tile load ----
    {
        const int pdx = tid >> 3;          // 0..31
        const int pdy = (tid & 7) * 4;     // 0,4,...,28
        const int g   = (x0 + pdx) * IMD + (y0 + pdy);   // 16B aligned
        float4 a = *(const float4*)(Cb0 + g);
        float4 b = *(const float4*)(Cb1 + g);
        float4 d = *(const float4*)(M1b + g);
        float4 e = *(const float4*)(M2b + g);
        sA[pdx][pdy] = a.x; sA[pdx][pdy+1] = a.y; sA[pdx][pdy+2] = a.z; sA[pdx][pdy+3] = a.w;
        sB[pdx][pdy] = b.x; sB[pdx][pdy+1] = b.y; sB[pdx][pdy+2] = b.z; sB[pdx][pdy+3] = b.w;
        sD[pdx][pdy] = d.x; sD[pdx][pdy+1] = d.y; sD[pdx][pdy+2] = d.z; sD[pdx][pdy+3] = d.w;
        sE[pdx][pdy] = e.x; sE[pdx][pdy+1] = e.y; sE[pdx][pdy+2] = e.z; sE[pdx][pdy+3] = e.w;
    }
    __syncthreads();

    // ---- Phase 2: x-fast compute, immediate owner-private writeback ----
    const int dx = tid & 31;        // lane -> x (gathers coalesced)
    const int wp = tid >> 5;        // warp 0..7
    const float xf = (float)(x0 + dx);

#pragma unroll
    for (int k = 0; k < 4; k++) {
        const int dy = wp + k * 8;
        const float c0 = sA[dx][dy];
        const float c1 = sB[dx][dy];
        const float m1 = sD[dx][dy];
        const float m2 = sE[dx][dy];
        const float yf = (float)(y0 + dy);

        float r0, r1, r2;

        // --- sample im1 at (x + c0, y + c1) ---
        {
            float px = xf + c0, py = yf + c1;
            float fx = floorf(px), cx = ceilf(px);
            float fy = floorf(py), cy = ceilf(py);
            float wfx = 1.0f - (px - fx), wcx = 1.0f - (cx - px);
            float wfy = 1.0f - (py - fy), wcy = 1.0f - (cy - py);
            int i00 = (int)fx + IMD * (int)fy;
            int i10 = (int)cx + IMD * (int)fy;
            int i01 = (int)fx + IMD * (int)cy;
            int i11 = (int)cx + IMD * (int)cy;
            i00 = min(max(i00, 0), HWPX - 1);
            i10 = min(max(i10, 0), HWPX - 1);
            i01 = min(max(i01, 0), HWPX - 1);
            i11 = min(max(i11, 0), HWPX - 1);
            float w00 = wfx * wfy, w10 = wcx * wfy;
            float w01 = wfx * wcy, w11 = wcx * wcy;
            const float* p0 = I1b;
            const float* p1 = I1b + HWPX;
            const float* p2 = I1b + 2 * HWPX;
            r0 = (((w00 * __ldg(p0 + i00) + w10 * __ldg(p0 + i10))
                  + w01 * __ldg(p0 + i01)) + w11 * __ldg(p0 + i11)) * m1;
            r1 = (((w00 * __ldg(p1 + i00) + w10 * __ldg(p1 + i10))
                  + w01 * __ldg(p1 + i01)) + w11 * __ldg(p1 + i11)) * m1;
            r2 = (((w00 * __ldg(p2 + i00) + w10 * __ldg(p2 + i10))
                  + w01 * __ldg(p2 + i01)) + w11 * __ldg(p2 + i11)) * m1;
        }
        // --- sample im2 at (x - c0, y - c1) ---
        {
            float px = xf - c0, py = yf - c1;
            float fx = floorf(px), cx = ceilf(px);
            float fy = floorf(py), cy = ceilf(py);
            float wfx = 1.0f - (px - fx), wcx = 1.0f - (cx - px);
            float wfy = 1.0f - (py - fy), wcy = 1.0f - (cy - py);
            int i00 = (int)fx + IMD * (int)fy;
            int i10 = (int)cx + IMD * (int)fy;
            int i01 = (int)fx + IMD * (int)cy;
            int i11 = (int)cx + IMD * (int)cy;
            i00 = min(max(i00, 0), HWPX - 1);
            i10 = min(max(i10, 0), HWPX - 1);
            i01 = min(max(i01, 0), HWPX - 1);
            i11 = min(max(i11, 0), HWPX - 1);
            float w00 = wfx * wfy, w10 = wcx * wfy;
            float w01 = wfx * wcy, w11 = wcx * wcy;
            const float* p0 = I2b;
            const float* p1 = I2b + HWPX;
            const float* p2 = I2b + 2 * HWPX;
            r0 += (((w00 * __ldg(p0 + i00) + w10 * __ldg(p0 + i10))
                   + w01 * __ldg(p0 + i01)) + w11 * __ldg(p0 + i11)) * m2;
            r1 += (((w00 * __ldg(p1 + i00) + w10 * __ldg(p1 + i10))
                   + w01 * __ldg(p1 + i01)) + w11 * __ldg(p1 + i11)) * m2;
            r2 += (((w00 * __ldg(p2 + i00) + w10 * __ldg(p2 + i10))
                   + w01 * __ldg(p2 + i01)) + w11 * __ldg(p2 + i11)) * m2;
        }

        // Owner-private cells: safe to overwrite without a barrier.
        sA[dx][dy] = r0;
        sB[dx][dy] = r1;
        sD[dx][dy] = r2;
    }
    __syncthreads();

    // ---- Phase 3: vectorized coalesced store ----
    {
        float* __restrict__ ob = out + (size_t)n * 3 * HWPX;
        const int pdx = tid >> 3;
        const int pdy = (tid & 7) * 4;
        const int g   = (x0 + pdx) * IMD + (y0 + pdy);   // 16B aligned
        float4 v;
        v.x = sA[pdx][pdy]; v.y = sA[pdx][pdy+1]; v.z = sA[pdx][pdy+2]; v.w = sA[pdx][pdy+3];
        *(float4*)(ob + g) = v;
        v.x = sB[pdx][pdy]; v.y = sB[pdx][pdy+1]; v.z = sB[pdx][pdy+2]; v.w = sB[pdx][pdy+3];
        *(float4*)(ob + HWPX + g) = v;
        v.x = sD[pdx][pdy]; v.y = sD[pdx][pdy+1]; v.z = sD[pdx][pdy+2]; v.w = sD[pdx][pdy+3];
        *(float4*)(ob + 2 * HWPX + g) = v;
    }
}

extern "C" void kernel_launch(void* const* d_in, const int* in_sizes, int n_in,
                              void* d_out, int out_size)
{
    const float* im1 = (const float*)d_in[0];
    const float* im2 = (const float*)d_in[1];
    const float* C   = (const float*)d_in[2];
    const float* M1  = (const float*)d_in[3];
    const float* M2  = (const float*)d_in[4];
    float* out = (float*)d_out;

    dim3 grid(IMD / 32, IMD / 32, 64);  // (7, 7, 64)
    vm_kernel<<<grid, 256>>>(im1, im2, C, M1, M2, out);
}

// round 12
// speedup vs baseline: 1.2887x; 1.0399x over previous
#include <cuda_runtime.h>

#define IMD 224
#define HWPX (IMD * IMD)

// Tile: 32 x-values (slow dim of p) x 32 y-values (fast dim).
// Phase 1: float4-vectorized coalesced loads of C0,C1,M1,M2 into padded smem.
// Phase 2: x-fast lanes; ALL 8 tap indices + weights (both images) computed
//          up front, then all 24 gathers issued as one flat batch for max MLP,
//          then a single FFMA reduction. Owner-private smem writeback.
// Phase 3: float4-vectorized coalesced stores.
__global__ __launch_bounds__(256, 5) void vm_kernel(
    const float* __restrict__ im1, const float* __restrict__ im2,
    const float* __restrict__ C,   const float* __restrict__ M1,
    const float* __restrict__ M2,  float* __restrict__ out)
{
    __shared__ float sA[32][33];  // C0  -> out c0
    __shared__ float sB[32][33];  // C1  -> out c1
    __shared__ float sD[32][33];  // M1  -> out c2
    __shared__ float sE[32][33];  // M2

    const int tid = threadIdx.x;
    const int n  = blockIdx.z;
    const int x0 = blockIdx.y * 32;
    const int y0 = blockIdx.x * 32;

    const float* __restrict__ Cb0 = C  + (size_t)n * 2 * HWPX;
    const float* __restrict__ Cb1 = Cb0 + HWPX;
    const float* __restrict__ M1b = M1 + (size_t)n * HWPX;
    const float* __restrict__ M2b = M2 + (size_t)n * HWPX;
    const float* __restrict__ I1b = im1 + (size_t)n * 3 * HWPX;
    const float* __restrict__ I2b = im2 + (size_t)n * 3 * HWPX;

    // ---- Phase 1: vectorized coalesced tile load ----
    {
        const int pdx = tid >> 3;          // 0..31
        const int pdy = (tid & 7) * 4;     // 0,4,...,28
        const int g   = (x0 + pdx) * IMD + (y0 + pdy);   // 16B aligned
        float4 a = *(const float4*)(Cb0 + g);
        float4 b = *(const float4*)(Cb1 + g);
        float4 d = *(const float4*)(M1b + g);
        float4 e = *(const float4*)(M2b + g);
        sA[pdx][pdy] = a.x; sA[pdx][pdy+1] = a.y; sA[pdx][pdy+2] = a.z; sA[pdx][pdy+3] = a.w;
        sB[pdx][pdy] = b.x; sB[pdx][pdy+1] = b.y; sB[pdx][pdy+2] = b.z; sB[pdx][pdy+3] = b.w;
        sD[pdx][pdy] = d.x; sD[pdx][pdy+1] = d.y; sD[pdx][pdy+2] = d.z; sD[pdx][pdy+3] = d.w;
        sE[pdx][pdy] = e.x; sE[pdx][pdy+1] = e.y; sE[pdx][pdy+2] = e.z; sE[pdx][pdy+3] = e.w;
    }
    __syncthreads();

    // ---- Phase 2: x-fast compute, flat 24-load gather bursts ----
    const int dx = tid & 31;        // lane -> x (gathers coalesced)
    const int wp = tid >> 5;        // warp 0..7
    const float xf = (float)(x0 + dx);

#pragma unroll
    for (int k = 0; k < 4; k++) {
        const int dy = wp + k * 8;
        const float c0 = sA[dx][dy];
        const float c1 = sB[dx][dy];
        const float m1 = sD[dx][dy];
        const float m2 = sE[dx][dy];
        const float yf = (float)(y0 + dy);

        // --- all indices + weights for both images up front ---
        int   idx[2][4];
        float w[2][4];
#pragma unroll
        for (int s = 0; s < 2; s++) {
            const float px = (s == 0) ? (xf + c0) : (xf - c0);
            const float py = (s == 0) ? (yf + c1) : (yf - c1);
            const int ifx = __float2int_rd(px);
            const int ify = __float2int_rd(py);
            const float fx = (float)ifx;
            const float fy = (float)ify;
            // ceil as in reference: cx = ceil(px) (== fx when px integral)
            const float cxv = ceilf(px);
            const float cyv = ceilf(py);
            const int icx = (int)cxv;
            const int icy = (int)cyv;
            const float wfx = 1.0f - (px - fx);
            const float wcx = 1.0f - (cxv - px);
            const float wfy = 1.0f - (py - fy);
            const float wcy = 1.0f - (cyv - py);
            int i00 = ifx + IMD * ify;
            int i10 = icx + IMD * ify;
            int i01 = ifx + IMD * icy;
            int i11 = icx + IMD * icy;
            idx[s][0] = min(max(i00, 0), HWPX - 1);
            idx[s][1] = min(max(i10, 0), HWPX - 1);
            idx[s][2] = min(max(i01, 0), HWPX - 1);
            idx[s][3] = min(max(i11, 0), HWPX - 1);
            w[s][0] = wfx * wfy;
            w[s][1] = wcx * wfy;
            w[s][2] = wfx * wcy;
            w[s][3] = wcx * wcy;
        }

        // --- flat gather burst: 24 independent loads ---
        float v1[3][4], v2[3][4];
#pragma unroll
        for (int c = 0; c < 3; c++) {
            const float* p1 = I1b + c * HWPX;
            const float* p2 = I2b + c * HWPX;
#pragma unroll
            for (int t = 0; t < 4; t++) {
                v1[c][t] = __ldg(p1 + idx[0][t]);
                v2[c][t] = __ldg(p2 + idx[1][t]);
            }
        }

        // --- reduction ---
#pragma unroll
        for (int c = 0; c < 3; c++) {
            float a = ((w[0][0] * v1[c][0] + w[0][1] * v1[c][1])
                     +  w[0][2] * v1[c][2]) + w[0][3] * v1[c][3];
            float b = ((w[1][0] * v2[c][0] + w[1][1] * v2[c][1])
                     +  w[1][2] * v2[c][2]) + w[1][3] * v2[c][3];
            float r = a * m1 + b * m2;
            // Owner-private cells: safe to overwrite without a barrier.
            if (c == 0) sA[dx][dy] = r;
            else if (c == 1) sB[dx][dy] = r;
            else sD[dx][dy] = r;
        }
    }
    __syncthreads();

    // ---- Phase 3: vectorized coalesced store ----
    {
        float* __restrict__ ob = out + (size_t)n * 3 * HWPX;
        const int pdx = tid >> 3;
        const int pdy = (tid & 7) * 4;
        const int g   = (x0 + pdx) * IMD + (y0 + pdy);   // 16B aligned
        float4 v;
        v.x = sA[pdx][pdy]; v.y = sA[pdx][pdy+1]; v.z = sA[pdx][pdy+2]; v.w = sA[pdx][pdy+3];
        *(float4*)(ob + g) = v;
        v.x = sB[pdx][pdy]; v.y = sB[pdx][pdy+1]; v.z = sB[pdx][pdy+2]; v.w = sB[pdx][pdy+3];
        *(float4*)(ob + HWPX + g) = v;
        v.x = sD[pdx][pdy]; v.y = sD[pdx][pdy+1]; v.z = sD[pdx][pdy+2]; v.w = sD[pdx][pdy+3];
        *(float4*)(ob + 2 * HWPX + g) = v;
    }
}

extern "C" void kernel_launch(void* const* d_in, const int* in_sizes, int n_in,
                              void* d_out, int out_size)
{
    const float* im1 = (const float*)d_in[0];
    const float* im2 = (const float*)d_in[1];
    const float* C   = (const float*)d_in[2];
    const float* M1  = (const float*)d_in[3];
    const float* M2  = (const float*)d_in[4];
    float* out = (float*)d_out;

    dim3 grid(IMD / 32, IMD / 32, 64);  // (7, 7, 64)
    vm_kernel<<<grid, 256>>>(im1, im2, C, M1, M2, out);
}